// round 9
// baseline (speedup 1.0000x reference)
#include <cuda_runtime.h>
#include <math.h>

#define VV 10000
#define EE 512
#define HH 1024
#define SS 64
#define BB 64

#define SBH (SS*BB*HH)
#define BH  (BB*HH)

typedef unsigned long long ull;

// ---------------- device scratch ----------------
__device__ float g_X0[3u * SBH];
__device__ float g_H1all[SBH];
__device__ float g_h0[BH];
__device__ float g_rh0[BH];
__device__ float g_z0[BH];
__device__ float g_z1[BH];
__device__ float g_cat1[BB * 2 * HH];   // [x1, h1]
__device__ float g_cat1h[BB * 2 * HH];  // [x1, r1*h1]

__device__ __forceinline__ float sigm(float x) { return 1.0f / (1.0f + __expf(-x)); }

// ---------------- packed f32x2 helpers (sm_103a FFMA2) ----------------
__device__ __forceinline__ void fma2(ull &c, ull a, ull b) {
    asm("fma.rn.f32x2 %0, %1, %2, %0;" : "+l"(c) : "l"(a), "l"(b));
}
__device__ __forceinline__ void add2(ull &c, ull a) {
    asm("add.rn.f32x2 %0, %0, %1;" : "+l"(c) : "l"(a));
}
__device__ __forceinline__ ull pk2(float lo, float hi) {
    ull r; asm("mov.b64 %0, {%1, %2};" : "=l"(r) : "f"(lo), "f"(hi)); return r;
}
__device__ __forceinline__ void unpk(ull v, float &lo, float &hi) {
    asm("mov.b64 {%0, %1}, %2;" : "=f"(lo), "=f"(hi) : "l"(v));
}

// ---------------- init ----------------
__global__ void k_init(const float* __restrict__ h_init) {
    int i = blockIdx.x * blockDim.x + threadIdx.x;
    if (i < BH) {
        g_h0[i] = h_init[i];
        int b = i >> 10, n = i & (HH - 1);
        g_cat1[b * 2 * HH + HH + n] = h_init[BH + i];
    }
}

// ---------------- embedding precompute GEMM (64x64x16, packed fma2) ----------------
__global__ __launch_bounds__(256) void k_embed(
    const int* __restrict__ ids, const float* __restrict__ emb,
    const float* __restrict__ Wr, const float* __restrict__ Wz, const float* __restrict__ Wh,
    const float* __restrict__ br, const float* __restrict__ bz, const float* __restrict__ bh)
{
    const int g = blockIdx.z;
    const float* __restrict__ W    = (g == 0) ? Wr : ((g == 1) ? Wz : Wh);
    const float* __restrict__ bias = (g == 0) ? br : ((g == 1) ? bz : bh);
    float* __restrict__ out = g_X0 + (size_t)g * SBH;

    __shared__ __align__(16) float As[16][68];
    __shared__ __align__(16) float Ws[16][64];
    const int tid = threadIdx.x;
    const int bm = blockIdx.y * 64, bn = blockIdx.x * 64;
    const int lr = tid >> 2, lk = (tid & 3) * 4;
    const int wk = tid >> 4, wn = (tid & 15) * 4;
    const int tx = tid & 15, ty = tid >> 4;
    const float* __restrict__ arow = emb + (size_t)ids[bm + lr] * EE + lk;

    ull accp[4][2];
#pragma unroll
    for (int i = 0; i < 4; i++) { accp[i][0] = 0ull; accp[i][1] = 0ull; }

    for (int k0 = 0; k0 < EE; k0 += 16) {
        float4 av = *(const float4*)(arow + k0);
        As[lk + 0][lr] = av.x; As[lk + 1][lr] = av.y;
        As[lk + 2][lr] = av.z; As[lk + 3][lr] = av.w;
        *(float4*)&Ws[wk][wn] = *(const float4*)(W + (size_t)(k0 + wk) * HH + bn + wn);
        __syncthreads();
#pragma unroll
        for (int kk = 0; kk < 16; kk++) {
            float4 a = *(const float4*)&As[kk][ty * 4];
            float4 w = *(const float4*)&Ws[kk][tx * 4];
            ulonglong2 wp = *reinterpret_cast<ulonglong2*>(&w);
            ull a0 = pk2(a.x, a.x), a1 = pk2(a.y, a.y);
            ull a2 = pk2(a.z, a.z), a3 = pk2(a.w, a.w);
            fma2(accp[0][0], a0, wp.x); fma2(accp[0][1], a0, wp.y);
            fma2(accp[1][0], a1, wp.x); fma2(accp[1][1], a1, wp.y);
            fma2(accp[2][0], a2, wp.x); fma2(accp[2][1], a2, wp.y);
            fma2(accp[3][0], a3, wp.x); fma2(accp[3][1], a3, wp.y);
        }
        __syncthreads();
    }
    float4 bv = *(const float4*)(bias + bn + tx * 4);
#pragma unroll
    for (int i = 0; i < 4; i++) {
        float c0, c1, c2, c3;
        unpk(accp[i][0], c0, c1); unpk(accp[i][1], c2, c3);
        int row = bm + ty * 4 + i;
        float* o = out + (size_t)row * HH + bn + tx * 4;
        o[0] = c0 + bv.x; o[1] = c1 + bv.y; o[2] = c2 + bv.z; o[3] = c3 + bv.w;
    }
}

// ---------------- k_out: logits = H1all @ Wout + bout (packed fma2) ----------------
__global__ __launch_bounds__(256) void k_out(
    const float* __restrict__ Wout, const float* __restrict__ bout,
    float* __restrict__ logits)
{
    __shared__ __align__(16) float As[16][68];
    __shared__ __align__(16) float Ws[16][64];
    const int tid = threadIdx.x;
    const int bm = blockIdx.y * 64, bn = blockIdx.x * 64;
    const int lr = tid >> 2, lk = (tid & 3) * 4;
    const int wk = tid >> 4, wn = (tid & 15) * 4;
    const int tx = tid & 15, ty = tid >> 4;
    const float* __restrict__ arow = g_H1all + (size_t)(bm + lr) * HH + lk;
    const bool wok = (bn + wn + 3) < VV;

    ull accp[4][2];
#pragma unroll
    for (int i = 0; i < 4; i++) { accp[i][0] = 0ull; accp[i][1] = 0ull; }

    for (int k0 = 0; k0 < HH; k0 += 16) {
        float4 av = *(const float4*)(arow + k0);
        As[lk + 0][lr] = av.x; As[lk + 1][lr] = av.y;
        As[lk + 2][lr] = av.z; As[lk + 3][lr] = av.w;
        float4 wv;
        const float* wp = Wout + (size_t)(k0 + wk) * VV;
        if (wok) {
            wv = *(const float4*)(wp + bn + wn);
        } else {
            wv.x = (bn + wn + 0 < VV) ? wp[bn + wn + 0] : 0.f;
            wv.y = (bn + wn + 1 < VV) ? wp[bn + wn + 1] : 0.f;
            wv.z = (bn + wn + 2 < VV) ? wp[bn + wn + 2] : 0.f;
            wv.w = (bn + wn + 3 < VV) ? wp[bn + wn + 3] : 0.f;
        }
        *(float4*)&Ws[wk][wn] = wv;
        __syncthreads();
#pragma unroll
        for (int kk = 0; kk < 16; kk++) {
            float4 a = *(const float4*)&As[kk][ty * 4];
            float4 w = *(const float4*)&Ws[kk][tx * 4];
            ulonglong2 wpk = *reinterpret_cast<ulonglong2*>(&w);
            ull a0 = pk2(a.x, a.x), a1 = pk2(a.y, a.y);
            ull a2 = pk2(a.z, a.z), a3 = pk2(a.w, a.w);
            fma2(accp[0][0], a0, wpk.x); fma2(accp[0][1], a0, wpk.y);
            fma2(accp[1][0], a1, wpk.x); fma2(accp[1][1], a1, wpk.y);
            fma2(accp[2][0], a2, wpk.x); fma2(accp[2][1], a2, wpk.y);
            fma2(accp[3][0], a3, wpk.x); fma2(accp[3][1], a3, wpk.y);
        }
        __syncthreads();
    }
#pragma unroll
    for (int i = 0; i < 4; i++) {
        float c[4];
        unpk(accp[i][0], c[0], c[1]); unpk(accp[i][1], c[2], c[3]);
        int row = bm + ty * 4 + i;
#pragma unroll
        for (int j = 0; j < 4; j++) {
            int col = bn + tx * 4 + j;
            if (col < VV) logits[(size_t)row * VV + col] = c[j] + bout[col];
        }
    }
}

// ================= step GEMM core v3: 8x2 register tiles, 1.5 B/MAC =================
// Output tile [64 x 8] per gate. 16 K-teams x 32 threads per gate (BK=8/chunk).
// Each compute thread: 8 rows x 2 cols = 16 outputs in 8 packed ull accumulators.
// Per kk: 2x LDS.128 (A rows) + 1x LDS.128 (W cols pre-dup) + 8 FFMA2.
// smem floats: As 16*2*8*68 = 17408 | Ws GATES*16*2*8*16 | Pq GATES*15*256 ull
#define G1_SMEM ((17408 + 4096) * 4 + 15*256*8)        // 116736 B
#define G2_SMEM ((17408 + 8192) * 4 + 2*15*256*8)      // 163840 B

template<int KT, int GATES>
__device__ __forceinline__ void core_gemm(
    const float* __restrict__ A, int lda,
    const float* __restrict__ W0, const float* __restrict__ W1,
    int bn, ull* __restrict__ acc)
{
    extern __shared__ float dyn[];
    float* As = dyn;                                   // [(team*2+buf)*544 + k*68 + row]
    float* Ws = dyn + 17408;                           // gate*4096 + [(team*2+buf)*128 + k*16 + cp*4]
    ull*   Pq = (ull*)(dyn + 17408 + GATES * 4096);

    constexpr int CH = KT / 128;       // chunks per team (BK=8)
    constexpr int KTEAM = KT / 16;
    const int tid = threadIdx.x;
    const int gate = (GATES == 2) ? (tid >> 9) : 0;
    const int t = tid & 511;
    const int team = t >> 5, u = t & 31;
    const int koff = team * KTEAM;
    const int rg = u >> 2, cp = u & 3;
    const float* __restrict__ W = (GATES == 2 && gate) ? W1 : W0;
    const float* __restrict__ Wb = W + (size_t)(koff + (u >> 2)) * HH + bn + (u & 3) * 2;
    const int asb = team * 2;

#pragma unroll
    for (int i = 0; i < 8; i++) acc[i] = 0ull;

    float w0s, w1s;

    if (GATES == 2) {
        // ---- A loader: 1 row per thread (both gates' threads load) ----
        const int ar = gate * 32 + u;
        const float* __restrict__ Ar = A + (size_t)ar * lda + koff;
        float a0[8];
        {
            float4 v0 = *(const float4*)(Ar);
            float4 v1 = *(const float4*)(Ar + 4);
            a0[0]=v0.x; a0[1]=v0.y; a0[2]=v0.z; a0[3]=v0.w;
            a0[4]=v1.x; a0[5]=v1.y; a0[6]=v1.z; a0[7]=v1.w;
            float2 wv = *(const float2*)(Wb);
            w0s = wv.x; w1s = wv.y;
        }
        {
            float* Ab = As + asb * 544;
#pragma unroll
            for (int j = 0; j < 8; j++) Ab[j * 68 + ar] = a0[j];
            float* Wd = Ws + gate * 4096 + asb * 128 + (u >> 2) * 16 + (u & 3) * 4;
            Wd[0] = w0s; Wd[1] = w0s; Wd[2] = w1s; Wd[3] = w1s;
        }
        __syncthreads();
        int buf = 0;
        for (int c = 0; c < CH; ++c) {
            const bool more = (c + 1 < CH);
            if (more) {
                const int k0 = (c + 1) * 8;
                float4 v0 = *(const float4*)(Ar + k0);
                float4 v1 = *(const float4*)(Ar + k0 + 4);
                a0[0]=v0.x; a0[1]=v0.y; a0[2]=v0.z; a0[3]=v0.w;
                a0[4]=v1.x; a0[5]=v1.y; a0[6]=v1.z; a0[7]=v1.w;
                float2 wv = *(const float2*)(Wb + (size_t)k0 * HH);
                w0s = wv.x; w1s = wv.y;
            }
            {
                const float* Ab = As + (asb + buf) * 544 + rg * 8;
                const float* Wd = Ws + gate * 4096 + (asb + buf) * 128 + cp * 4;
#pragma unroll
                for (int kk = 0; kk < 8; ++kk) {
                    float4 lo = *(const float4*)(Ab + kk * 68);
                    float4 hi = *(const float4*)(Ab + kk * 68 + 4);
                    float4 wd = *(const float4*)(Wd + kk * 16);
                    ulonglong2 pl = *reinterpret_cast<ulonglong2*>(&lo);
                    ulonglong2 ph = *reinterpret_cast<ulonglong2*>(&hi);
                    ulonglong2 wp = *reinterpret_cast<ulonglong2*>(&wd);
                    fma2(acc[0], pl.x, wp.x); fma2(acc[1], pl.x, wp.y);
                    fma2(acc[2], pl.y, wp.x); fma2(acc[3], pl.y, wp.y);
                    fma2(acc[4], ph.x, wp.x); fma2(acc[5], ph.x, wp.y);
                    fma2(acc[6], ph.y, wp.x); fma2(acc[7], ph.y, wp.y);
                }
            }
            if (more) {
                float* Ab = As + (asb + (buf ^ 1)) * 544;
#pragma unroll
                for (int j = 0; j < 8; j++) Ab[j * 68 + ar] = a0[j];
                float* Wd = Ws + gate * 4096 + (asb + (buf ^ 1)) * 128 + (u >> 2) * 16 + (u & 3) * 4;
                Wd[0] = w0s; Wd[1] = w0s; Wd[2] = w1s; Wd[3] = w1s;
                __syncthreads();
                buf ^= 1;
            }
        }
    } else {
        // ---- single gate: loader has 2 rows (u, u+32) ----
        const float* __restrict__ Ar0 = A + (size_t)u * lda + koff;
        const float* __restrict__ Ar1 = A + (size_t)(u + 32) * lda + koff;
        float a0[16];
        {
            float4 v0 = *(const float4*)(Ar0);
            float4 v1 = *(const float4*)(Ar0 + 4);
            float4 v2 = *(const float4*)(Ar1);
            float4 v3 = *(const float4*)(Ar1 + 4);
            a0[0]=v0.x; a0[1]=v0.y; a0[2]=v0.z; a0[3]=v0.w;
            a0[4]=v1.x; a0[5]=v1.y; a0[6]=v1.z; a0[7]=v1.w;
            a0[8]=v2.x; a0[9]=v2.y; a0[10]=v2.z; a0[11]=v2.w;
            a0[12]=v3.x; a0[13]=v3.y; a0[14]=v3.z; a0[15]=v3.w;
            float2 wv = *(const float2*)(Wb);
            w0s = wv.x; w1s = wv.y;
        }
        {
            float* Ab = As + asb * 544;
#pragma unroll
            for (int j = 0; j < 8; j++) {
                Ab[j * 68 + u]      = a0[j];
                Ab[j * 68 + u + 32] = a0[8 + j];
            }
            float* Wd = Ws + asb * 128 + (u >> 2) * 16 + (u & 3) * 4;
            Wd[0] = w0s; Wd[1] = w0s; Wd[2] = w1s; Wd[3] = w1s;
        }
        __syncthreads();
        int buf = 0;
        for (int c = 0; c < CH; ++c) {
            const bool more = (c + 1 < CH);
            if (more) {
                const int k0 = (c + 1) * 8;
                float4 v0 = *(const float4*)(Ar0 + k0);
                float4 v1 = *(const float4*)(Ar0 + k0 + 4);
                float4 v2 = *(const float4*)(Ar1 + k0);
                float4 v3 = *(const float4*)(Ar1 + k0 + 4);
                a0[0]=v0.x; a0[1]=v0.y; a0[2]=v0.z; a0[3]=v0.w;
                a0[4]=v1.x; a0[5]=v1.y; a0[6]=v1.z; a0[7]=v1.w;
                a0[8]=v2.x; a0[9]=v2.y; a0[10]=v2.z; a0[11]=v2.w;
                a0[12]=v3.x; a0[13]=v3.y; a0[14]=v3.z; a0[15]=v3.w;
                float2 wv = *(const float2*)(Wb + (size_t)k0 * HH);
                w0s = wv.x; w1s = wv.y;
            }
            {
                const float* Ab = As + (asb + buf) * 544 + rg * 8;
                const float* Wd = Ws + (asb + buf) * 128 + cp * 4;
#pragma unroll
                for (int kk = 0; kk < 8; ++kk) {
                    float4 lo = *(const float4*)(Ab + kk * 68);
                    float4 hi = *(const float4*)(Ab + kk * 68 + 4);
                    float4 wd = *(const float4*)(Wd + kk * 16);
                    ulonglong2 pl = *reinterpret_cast<ulonglong2*>(&lo);
                    ulonglong2 ph = *reinterpret_cast<ulonglong2*>(&hi);
                    ulonglong2 wp = *reinterpret_cast<ulonglong2*>(&wd);
                    fma2(acc[0], pl.x, wp.x); fma2(acc[1], pl.x, wp.y);
                    fma2(acc[2], pl.y, wp.x); fma2(acc[3], pl.y, wp.y);
                    fma2(acc[4], ph.x, wp.x); fma2(acc[5], ph.x, wp.y);
                    fma2(acc[6], ph.y, wp.x); fma2(acc[7], ph.y, wp.y);
                }
            }
            if (more) {
                float* Ab = As + (asb + (buf ^ 1)) * 544;
#pragma unroll
                for (int j = 0; j < 8; j++) {
                    Ab[j * 68 + u]      = a0[j];
                    Ab[j * 68 + u + 32] = a0[8 + j];
                }
                float* Wd = Ws + (asb + (buf ^ 1)) * 128 + (u >> 2) * 16 + (u & 3) * 4;
                Wd[0] = w0s; Wd[1] = w0s; Wd[2] = w1s; Wd[3] = w1s;
                __syncthreads();
                buf ^= 1;
            }
        }
    }

    // ---- 16-way reduction per gate: teams 1..15 -> Pq, team0 accumulates ----
    if (team != 0) {
        ull* p = Pq + ((size_t)gate * 15 + (team - 1)) * 256 + u * 8;
#pragma unroll
        for (int i = 0; i < 8; i++) p[i] = acc[i];
    }
    __syncthreads();
    if (team == 0) {
#pragma unroll 1
        for (int r = 0; r < 15; r++) {
            ull* p = Pq + ((size_t)gate * 15 + r) * 256 + u * 8;
#pragma unroll
            for (int i = 0; i < 8; i++) add2(acc[i], p[i]);
        }
    }
}

// ---------------- step kernels ----------------

// r0 & z0: sigma(X0[g][ts] + h0 @ W{r,z}0[E:,:]); r-branch stores r*h0
__global__ __launch_bounds__(1024, 1) void k_gates0(int ts,
    const float* __restrict__ Wr0, const float* __restrict__ Wz0)
{
    const int bn = blockIdx.x * 8;
    ull acc[8];
    core_gemm<HH, 2>(g_h0, HH, Wr0 + (size_t)EE * HH, Wz0 + (size_t)EE * HH, bn, acc);
    if ((threadIdx.x & 511) < 32) {
        const int gate = threadIdx.x >> 9;
        const int u = threadIdx.x & 31, rg = u >> 2, cp = u & 3;
        const float* X = g_X0 + (size_t)gate * SBH + (size_t)ts * BH;
#pragma unroll
        for (int p = 0; p < 4; p++)
#pragma unroll
            for (int c = 0; c < 2; c++) {
                float va, vb; unpk(acc[2 * p + c], va, vb);
                int r = rg * 8 + 2 * p, n = bn + cp * 2 + c;
                int i0 = r * HH + n, i1 = (r + 1) * HH + n;
                float s0 = sigm(va + X[i0]);
                float s1 = sigm(vb + X[i1]);
                if (gate == 0) { g_rh0[i0] = s0 * g_h0[i0]; g_rh0[i1] = s1 * g_h0[i1]; }
                else           { g_z0[i0] = s0;             g_z0[i1] = s1; }
            }
    }
}

// hh0 = sigma(X0[2][ts] + rh0 @ Wh0[E:,:]); h0 <- (1-z)h + z*hh
__global__ __launch_bounds__(512, 1) void k_cand0(int ts, const float* __restrict__ Wh0)
{
    const int bn = blockIdx.x * 8;
    ull acc[8];
    core_gemm<HH, 1>(g_rh0, HH, Wh0 + (size_t)EE * HH, nullptr, bn, acc);
    if (threadIdx.x < 32) {
        const int u = threadIdx.x, rg = u >> 2, cp = u & 3;
        const float* X = g_X0 + 2ull * SBH + (size_t)ts * BH;
#pragma unroll
        for (int p = 0; p < 4; p++)
#pragma unroll
            for (int c = 0; c < 2; c++) {
                float va, vb; unpk(acc[2 * p + c], va, vb);
                int r = rg * 8 + 2 * p, n = bn + cp * 2 + c;
                int i0 = r * HH + n, i1 = (r + 1) * HH + n;
                float h0a = g_h0[i0], z0a = g_z0[i0];
                float h0b = g_h0[i1], z0b = g_z0[i1];
                g_h0[i0] = (1.f - z0a) * h0a + z0a * sigm(va + X[i0]);
                g_h0[i1] = (1.f - z0b) * h0b + z0b * sigm(vb + X[i1]);
            }
    }
}

// x1 = sigma(h0 @ Wfc + bfc)
__global__ __launch_bounds__(512, 1) void k_fc(
    const float* __restrict__ Wfc, const float* __restrict__ bfc)
{
    const int bn = blockIdx.x * 8;
    ull acc[8];
    core_gemm<HH, 1>(g_h0, HH, Wfc, nullptr, bn, acc);
    if (threadIdx.x < 32) {
        const int u = threadIdx.x, rg = u >> 2, cp = u & 3;
#pragma unroll
        for (int p = 0; p < 4; p++)
#pragma unroll
            for (int c = 0; c < 2; c++) {
                float va, vb; unpk(acc[2 * p + c], va, vb);
                int r = rg * 8 + 2 * p, n = bn + cp * 2 + c;
                float x1a = sigm(va + bfc[n]);
                float x1b = sigm(vb + bfc[n]);
                g_cat1[r * 2 * HH + n]        = x1a;
                g_cat1h[r * 2 * HH + n]       = x1a;
                g_cat1[(r + 1) * 2 * HH + n]  = x1b;
                g_cat1h[(r + 1) * 2 * HH + n] = x1b;
            }
    }
}

// r1 & z1 over [x1, h1] (K=2048)
__global__ __launch_bounds__(1024, 1) void k_gates1(
    const float* __restrict__ Wr1, const float* __restrict__ Wz1,
    const float* __restrict__ br1, const float* __restrict__ bz1)
{
    const int bn = blockIdx.x * 8;
    ull acc[8];
    core_gemm<2 * HH, 2>(g_cat1, 2 * HH, Wr1, Wz1, bn, acc);
    if ((threadIdx.x & 511) < 32) {
        const int gate = threadIdx.x >> 9;
        const int u = threadIdx.x & 31, rg = u >> 2, cp = u & 3;
        const float* bias = gate ? bz1 : br1;
#pragma unroll
        for (int p = 0; p < 4; p++)
#pragma unroll
            for (int c = 0; c < 2; c++) {
                float va, vb; unpk(acc[2 * p + c], va, vb);
                int r = rg * 8 + 2 * p, n = bn + cp * 2 + c;
                float s0 = sigm(va + bias[n]);
                float s1 = sigm(vb + bias[n]);
                if (gate == 0) {
                    g_cat1h[r * 2 * HH + HH + n]       = s0 * g_cat1[r * 2 * HH + HH + n];
                    g_cat1h[(r + 1) * 2 * HH + HH + n] = s1 * g_cat1[(r + 1) * 2 * HH + HH + n];
                } else {
                    g_z1[r * HH + n]       = s0;
                    g_z1[(r + 1) * HH + n] = s1;
                }
            }
    }
}

// hh1 over [x1, r1*h1] (K=2048); h1 update + H1all store
__global__ __launch_bounds__(512, 1) void k_cand1(int ts,
    const float* __restrict__ Wh1, const float* __restrict__ bh1)
{
    const int bn = blockIdx.x * 8;
    ull acc[8];
    core_gemm<2 * HH, 1>(g_cat1h, 2 * HH, Wh1, nullptr, bn, acc);
    if (threadIdx.x < 32) {
        const int u = threadIdx.x, rg = u >> 2, cp = u & 3;
#pragma unroll
        for (int p = 0; p < 4; p++)
#pragma unroll
            for (int c = 0; c < 2; c++) {
                float va, vb; unpk(acc[2 * p + c], va, vb);
                int r = rg * 8 + 2 * p, n = bn + cp * 2 + c;
#pragma unroll
                for (int q = 0; q < 2; q++) {
                    int rr = r + q;
                    float hv = (q == 0) ? va : vb;
                    float hh = sigm(hv + bh1[n]);
                    float h1 = g_cat1[rr * 2 * HH + HH + n];
                    float z  = g_z1[rr * HH + n];
                    float hn = (1.f - z) * h1 + z * hh;
                    g_cat1[rr * 2 * HH + HH + n] = hn;
                    g_H1all[(size_t)ts * BH + rr * HH + n] = hn;
                }
            }
    }
}

// h_final = [h0, h1] appended after logits
__global__ void k_hfinal(float* __restrict__ out) {
    int i = blockIdx.x * blockDim.x + threadIdx.x;
    if (i < BH) {
        out[i] = g_h0[i];
        int b = i >> 10, n = i & (HH - 1);
        out[BH + i] = g_cat1[b * 2 * HH + HH + n];
    }
}

extern "C" void kernel_launch(void* const* d_in, const int* in_sizes, int n_in,
                              void* d_out, int out_size)
{
    const int*   ids    = (const int*)d_in[0];
    const float* h_init = (const float*)d_in[1];
    const float* emb    = (const float*)d_in[2];
    const float* Wr0 = (const float*)d_in[3],  *Wz0 = (const float*)d_in[4],  *Wh0 = (const float*)d_in[5];
    const float* br0 = (const float*)d_in[6],  *bz0 = (const float*)d_in[7],  *bh0 = (const float*)d_in[8];
    const float* Wr1 = (const float*)d_in[9],  *Wz1 = (const float*)d_in[10], *Wh1 = (const float*)d_in[11];
    const float* br1 = (const float*)d_in[12], *bz1 = (const float*)d_in[13], *bh1 = (const float*)d_in[14];
    const float* Wfc = (const float*)d_in[15], *bfc = (const float*)d_in[16];
    const float* Wout = (const float*)d_in[17], *bout = (const float*)d_in[18];
    float* out = (float*)d_out;

    cudaFuncSetAttribute(k_gates0, cudaFuncAttributeMaxDynamicSharedMemorySize, G2_SMEM);
    cudaFuncSetAttribute(k_gates1, cudaFuncAttributeMaxDynamicSharedMemorySize, G2_SMEM);
    cudaFuncSetAttribute(k_cand0,  cudaFuncAttributeMaxDynamicSharedMemorySize, G1_SMEM);
    cudaFuncSetAttribute(k_fc,     cudaFuncAttributeMaxDynamicSharedMemorySize, G1_SMEM);
    cudaFuncSetAttribute(k_cand1,  cudaFuncAttributeMaxDynamicSharedMemorySize, G1_SMEM);

    k_init<<<(BH + 255) / 256, 256>>>(h_init);
    k_embed<<<dim3(HH / 64, (SS * BB) / 64, 3), 256>>>(ids, emb, Wr0, Wz0, Wh0, br0, bz0, bh0);

    for (int t = 0; t < SS; ++t) {
        k_gates0<<<HH / 8, 1024, G2_SMEM>>>(t, Wr0, Wz0);
        k_cand0<<<HH / 8, 512, G1_SMEM>>>(t, Wh0);
        k_fc<<<HH / 8, 512, G1_SMEM>>>(Wfc, bfc);
        k_gates1<<<HH / 8, 1024, G2_SMEM>>>(Wr1, Wz1, br1, bz1);
        k_cand1<<<HH / 8, 512, G1_SMEM>>>(t, Wh1, bh1);
    }

    k_out<<<dim3((VV + 63) / 64, (SS * BB) / 64), 256>>>(Wout, bout, out);
    k_hfinal<<<(BH + 255) / 256, 256>>>(out + (size_t)SS * BB * VV);
}